// round 8
// baseline (speedup 1.0000x reference)
#include <cuda_runtime.h>

// Problem constants (from reference)
#define G_ 4096
#define U_ 50
#define M_ 20
#define D_ 64
#define S_ 64
#define FACTOR_ 0.5f

// 25 warps, each warp owns 2 users (2w, 2w+1) as two interleaved streams.
// Full warp per row: lane l holds dims 2l, 2l+1 (float2) -> LDG.64 = 256B row.
#define NWARPS 25
#define NTHREADS (NWARPS * 32)   // 800

__global__ __launch_bounds__(NTHREADS, 2)
void group_embedding_kernel(const int*   __restrict__ group_user,      // [G,U]
                            const int*   __restrict__ behavior_ids,    // [G,U,M]
                            const float* __restrict__ behavior_counts, // [G,U,M]
                            const int*   __restrict__ target_user,     // [G]
                            const float* __restrict__ similarity_vec,  // [100000,S]
                            const float* __restrict__ user_emb_w,      // [100000,D]
                            const float* __restrict__ item_emb_w,      // [100000,D]
                            float*       __restrict__ out)             // [G,D]
{
    const int g    = blockIdx.x;
    const int tid  = threadIdx.x;
    const int warp = tid >> 5;
    const int lane = tid & 31;

    __shared__ __align__(16) float  partials[NWARPS][D_]; // 6.4KB
    __shared__ __align__(16) float  red[8][D_];           // 2KB
    // Per-warp 40 (id,count) float2 pairs: [u0 m0..19][u1 m0..19], 320B/row.
    __shared__ __align__(16) float2 wbeh[NWARPS][2 * M_]; // 8KB

    // ---- Per-warp staging: 40 contiguous pairs, coalesced LDG ----
    {
        const int base = g * (U_ * M_) + warp * (2 * M_);
        wbeh[warp][lane] = make_float2(__int_as_float(behavior_ids[base + lane]),
                                       behavior_counts[base + lane]);
        if (lane < 8)
            wbeh[warp][32 + lane] =
                make_float2(__int_as_float(behavior_ids[base + 32 + lane]),
                            behavior_counts[base + 32 + lane]);
    }

    // Two user ids for this warp (broadcast loads).
    const int uid0 = group_user[g * U_ + 2 * warp];
    const int uid1 = group_user[g * U_ + 2 * warp + 1];

    // Early user-embedding loads (overlap the gather chains).
    const float2 ue0 = *reinterpret_cast<const float2*>(
        user_emb_w + (size_t)uid0 * D_ + 2 * lane);
    const float2 ue1 = *reinterpret_cast<const float2*>(
        user_emb_w + (size_t)uid1 * D_ + 2 * lane);

    // Similarity dots (full-warp reduce, 2 dims per lane).
    const int tgt = target_user[g];
    const float2 tsim = *reinterpret_cast<const float2*>(
        similarity_vec + (size_t)tgt * S_ + 2 * lane);
    const float2 os0 = *reinterpret_cast<const float2*>(
        similarity_vec + (size_t)uid0 * S_ + 2 * lane);
    const float2 os1 = *reinterpret_cast<const float2*>(
        similarity_vec + (size_t)uid1 * S_ + 2 * lane);
    float d0 = tsim.x * os0.x + tsim.y * os0.y;
    float d1 = tsim.x * os1.x + tsim.y * os1.y;
    #pragma unroll
    for (int o = 16; o; o >>= 1) {
        d0 += __shfl_xor_sync(0xffffffffu, d0, o);
        d1 += __shfl_xor_sync(0xffffffffu, d1, o);
    }
    const float sim0 = FACTOR_ * d0;
    const float sim1 = FACTOR_ * d1;

    __syncwarp();   // own warp's wbeh slice ready

    // ---- Gather loops: two independent float2 streams, 2 behaviors/user/iter.
    const float4* f4 = reinterpret_cast<const float4*>(&wbeh[warp][0]);
    float2 ub0 = make_float2(0.f, 0.f);
    float2 ub1 = make_float2(0.f, 0.f);
    #pragma unroll
    for (int mb = 0; mb < M_ / 2; mb++) {
        // u0 pairs (2mb, 2mb+1) and u1 pairs (2mb, 2mb+1): one LDS.128 each.
        const float4 pa = f4[mb];            // (idA0,cA0, idA1,cA1)
        const float4 pb = f4[M_ / 2 + mb];   // (idB0,cB0, idB1,cB1)

        const float2 ea0 = *reinterpret_cast<const float2*>(
            item_emb_w + (size_t)__float_as_int(pa.x) * D_ + 2 * lane);
        const float2 ea1 = *reinterpret_cast<const float2*>(
            item_emb_w + (size_t)__float_as_int(pa.z) * D_ + 2 * lane);
        const float2 eb0 = *reinterpret_cast<const float2*>(
            item_emb_w + (size_t)__float_as_int(pb.x) * D_ + 2 * lane);
        const float2 eb1 = *reinterpret_cast<const float2*>(
            item_emb_w + (size_t)__float_as_int(pb.z) * D_ + 2 * lane);

        ub0.x += ea0.x * pa.y;  ub0.y += ea0.y * pa.y;
        ub0.x += ea1.x * pa.w;  ub0.y += ea1.y * pa.w;
        ub1.x += eb0.x * pb.y;  ub1.y += eb0.y * pb.y;
        ub1.x += eb1.x * pb.w;  ub1.y += eb1.y * pb.w;
    }

    // Personalize, weight by sim, fold both users in registers.
    float2 acc;
    acc.x = ub0.x * ue0.x * sim0 + ub1.x * ue1.x * sim1;
    acc.y = ub0.y * ue0.y * sim0 + ub1.y * ue1.y * sim1;

    *reinterpret_cast<float2*>(&partials[warp][2 * lane]) = acc;
    __syncthreads();

    // ---- Two-stage deterministic reduce over 25 rows ----
    if (tid < 512) {
        const int d = tid & 63;
        const int r = tid >> 6;      // 0..7
        float s = 0.f;
        #pragma unroll
        for (int p = r; p < NWARPS; p += 8)   // rows r, r+8, r+16, (r+24 if r==0)
            s += partials[p][d];
        red[r][d] = s;
    }
    __syncthreads();

    if (tid < D_) {
        float s = 0.f;
        #pragma unroll
        for (int r = 0; r < 8; r++)
            s += red[r][tid];
        out[(size_t)g * D_ + tid] = s;
    }
}

extern "C" void kernel_launch(void* const* d_in, const int* in_sizes, int n_in,
                              void* d_out, int out_size) {
    const int*   group_user      = (const int*)  d_in[0];
    const int*   behavior_ids    = (const int*)  d_in[1];
    const float* behavior_counts = (const float*)d_in[2];
    const int*   target_user     = (const int*)  d_in[3];
    const float* similarity_vec  = (const float*)d_in[4];
    const float* user_emb_w      = (const float*)d_in[5];
    const float* item_emb_w      = (const float*)d_in[6];
    float* out = (float*)d_out;

    group_embedding_kernel<<<G_, NTHREADS>>>(
        group_user, behavior_ids, behavior_counts, target_user,
        similarity_vec, user_emb_w, item_emb_w, out);
}